// round 6
// baseline (speedup 1.0000x reference)
#include <cuda_runtime.h>
#include <cstdint>

// ---------------- problem constants ----------------
constexpr int Bb   = 8;
constexpr int Ll   = 2048;
constexpr int Tt   = Bb * Ll;      // 16384 tokens
constexpr int Dd   = 512;
constexpr int Kk   = 4096;
constexpr int QN   = Tt * Dd;      // 8388608
constexpr int LOSS_OFF = QN;       // scalar loss position
constexpr int IDX_OFF  = QN + 1;   // indices (as float) position

#define DECAYF 0.99f
#define EPSF   1e-5f

// ---------------- device scratch (no allocation allowed) ----------------
__device__ float g_c2[Kk];
__device__ float g_x2[Tt];
__device__ float g_partS[2][Tt];
__device__ int   g_partI[2][Tt];
__device__ int   g_idx[Tt];
__device__ float g_counts[Kk];
__device__ float g_avgc[Kk];
__device__ float g_dw[(size_t)Kk * Dd];
__device__ float g_cbnew[(size_t)Kk * Dd];
__device__ float g_N;
__device__ float g_loss;

// ---------------- f32x2 helpers (Blackwell packed fp32) ----------------
__device__ __forceinline__ unsigned long long pack2(float lo, float hi) {
    unsigned long long r;
    asm("mov.b64 %0, {%1, %2};" : "=l"(r) : "f"(lo), "f"(hi));
    return r;
}
__device__ __forceinline__ void unpack2(unsigned long long v, float& lo, float& hi) {
    asm("mov.b64 {%0, %1}, %2;" : "=f"(lo), "=f"(hi) : "l"(v));
}
__device__ __forceinline__ void ffma2(unsigned long long& d, unsigned long long a, unsigned long long b) {
    asm("fma.rn.f32x2 %0, %1, %2, %3;" : "=l"(d) : "l"(a), "l"(b), "l"(d));
}

// ---------------- K0: zero scratch ----------------
__global__ void k_zero() {
    int gid = blockIdx.x * blockDim.x + threadIdx.x;
    int stride = gridDim.x * blockDim.x;
    int n = Kk * Dd;
    for (int i = gid; i < n; i += stride) g_dw[i] = 0.f;
    for (int i = gid; i < Kk; i += stride) g_counts[i] = 0.f;
    if (gid == 0) { g_N = 0.f; g_loss = 0.f; }
}

// ---------------- K1: c2[k] = ||codebook[k]||^2 ----------------
__global__ void k_c2(const float* __restrict__ cb) {
    int w = (blockIdx.x * blockDim.x + threadIdx.x) >> 5;
    int lane = threadIdx.x & 31;
    if (w >= Kk) return;
    const float4* row = (const float4*)(cb + (size_t)w * Dd);
    float s = 0.f;
    #pragma unroll
    for (int i = lane; i < Dd / 4; i += 32) {
        float4 v = __ldg(row + i);
        s += v.x * v.x + v.y * v.y + v.z * v.z + v.w * v.w;
    }
    #pragma unroll
    for (int o = 16; o; o >>= 1) s += __shfl_xor_sync(0xffffffffu, s, o);
    if (lane == 0) g_c2[w] = s;
}

// ---------------- K1b: x2[t] = ||x[t]||^2 ----------------
__global__ void k_x2(const float* __restrict__ x) {
    int w = (blockIdx.x * blockDim.x + threadIdx.x) >> 5;
    int lane = threadIdx.x & 31;
    if (w >= Tt) return;
    const float4* row = (const float4*)(x + (size_t)w * Dd);
    float s = 0.f;
    #pragma unroll
    for (int i = lane; i < Dd / 4; i += 32) {
        float4 v = __ldg(row + i);
        s += v.x * v.x + v.y * v.y + v.z * v.z + v.w * v.w;
    }
    #pragma unroll
    for (int o = 16; o; o >>= 1) s += __shfl_xor_sync(0xffffffffu, s, o);
    if (lane == 0) g_x2[w] = s;
}

// ---------------- K2: fused distance GEMM + partial argmin ----------------
// 256 threads, TM=128 tokens x TN=128 codes, KC=16, K split in 2 (gridDim.y).
// score = (x2 - 2*xc) + c2, rounded step-by-step to match the reference's fp32
// rounding grid (x2 ~ 512 dominates -> ulp(d2) ~ 6e-5; comparisons must happen
// on that grid or near-ties flip vs the reference).
constexpr int TM = 128, TN = 128, KC = 16, KSPLIT = 2;
constexpr int KHALF  = Kk / KSPLIT;       // 2048 codes per block
constexpr int SSTRIDE = TN + 4;           // 132 floats, 16B-multiple, pad kills conflicts

__global__ __launch_bounds__(256, 2)
void k_dist(const float* __restrict__ x, const float* __restrict__ cb) {
    __shared__ float Xs[2][KC][SSTRIDE];
    __shared__ float Cs[2][KC][SSTRIDE];

    const int tid = threadIdx.x;
    const int ty = tid >> 4;          // 0..15  -> token groups
    const int tx = tid & 15;          // 0..15  -> code groups
    const int tb = blockIdx.x * TM;   // token tile base
    const int kb0 = blockIdx.y * KHALF;

    float4 xr[2], cr[2];              // staging registers

    float best[8];
    int   bidx[8];
    #pragma unroll
    for (int i = 0; i < 8; i++) { best[i] = 3.4e38f; bidx[i] = 0; }

    // x2 for the 8 tokens this thread owns (slot i -> local token tl)
    float x2s[8];
    #pragma unroll
    for (int i = 0; i < 8; i++) {
        int p = i >> 1, e = i & 1;
        int tl = (p < 2) ? (ty * 4 + p * 2 + e) : (64 + ty * 4 + (p - 2) * 2 + e);
        x2s[i] = g_x2[tb + tl];
    }

    unsigned long long acc[4][8];     // [token-pair][code], f32x2

    auto ldStage = [&](int s) {
        int kt = s >> 5;              // ktile (32 dchunks each)
        int dc = s & 31;
        int db = dc * KC;
        int kb = kb0 + kt * TN;
        #pragma unroll
        for (int i = 0; i < 2; i++) {
            int f = tid + 256 * i;
            int col = f & 127;
            int kq  = f >> 7;         // 0..3 (float4 within KC=16)
            xr[i] = __ldg((const float4*)(x  + (size_t)(tb + col) * Dd + db + kq * 4));
            cr[i] = __ldg((const float4*)(cb + (size_t)(kb + col) * Dd + db + kq * 4));
        }
    };
    auto stStage = [&](int buf) {
        #pragma unroll
        for (int i = 0; i < 2; i++) {
            int f = tid + 256 * i;
            int col = f & 127;
            int kq  = f >> 7;
            Xs[buf][kq * 4 + 0][col] = xr[i].x;
            Xs[buf][kq * 4 + 1][col] = xr[i].y;
            Xs[buf][kq * 4 + 2][col] = xr[i].z;
            Xs[buf][kq * 4 + 3][col] = xr[i].w;
            Cs[buf][kq * 4 + 0][col] = cr[i].x;
            Cs[buf][kq * 4 + 1][col] = cr[i].y;
            Cs[buf][kq * 4 + 2][col] = cr[i].z;
            Cs[buf][kq * 4 + 3][col] = cr[i].w;
        }
    };

    constexpr int NSTG = (KHALF / TN) * (Dd / KC);  // 16 * 32 = 512 stages
    ldStage(0);

    for (int s = 0; s < NSTG; ++s) {
        int buf = s & 1;
        stStage(buf);
        if (s + 1 < NSTG) ldStage(s + 1);
        __syncthreads();

        if ((s & 31) == 0) {
            #pragma unroll
            for (int p = 0; p < 4; p++)
                #pragma unroll
                for (int j = 0; j < 8; j++) acc[p][j] = 0ull;
        }

        #pragma unroll
        for (int kk = 0; kk < KC; kk++) {
            ulonglong2 xA = *(const ulonglong2*)&Xs[buf][kk][ty * 4];
            ulonglong2 xB = *(const ulonglong2*)&Xs[buf][kk][64 + ty * 4];
            float4 cA = *(const float4*)&Cs[buf][kk][tx * 4];
            float4 cB = *(const float4*)&Cs[buf][kk][64 + tx * 4];
            float cv[8] = {cA.x, cA.y, cA.z, cA.w, cB.x, cB.y, cB.z, cB.w};
            #pragma unroll
            for (int j = 0; j < 8; j++) {
                unsigned long long cj = pack2(cv[j], cv[j]);
                ffma2(acc[0][j], xA.x, cj);
                ffma2(acc[1][j], xA.y, cj);
                ffma2(acc[2][j], xB.x, cj);
                ffma2(acc[3][j], xB.y, cj);
            }
        }

        if ((s & 31) == 31) {                       // ktile epilogue
            int kt = s >> 5;
            int kb = kb0 + kt * TN;
            float4 c2a = __ldg((const float4*)(g_c2 + kb + tx * 4));
            float4 c2b = __ldg((const float4*)(g_c2 + kb + 64 + tx * 4));
            float c2v[8] = {c2a.x, c2a.y, c2a.z, c2a.w, c2b.x, c2b.y, c2b.z, c2b.w};
            #pragma unroll
            for (int j = 0; j < 8; j++) {
                int code = kb + ((j < 4) ? (tx * 4 + j) : (64 + tx * 4 + (j - 4)));
                #pragma unroll
                for (int p = 0; p < 4; p++) {
                    float lo, hi;
                    unpack2(acc[p][j], lo, hi);
                    int i0 = p * 2;     // best[] slot for lo
                    // d2 = rn(rn(x2 - rn(2*xc)) + c2)  -- match reference rounding
                    float s0 = __fadd_rn(__fsub_rn(x2s[i0],     __fmul_rn(2.0f, lo)), c2v[j]);
                    float s1 = __fadd_rn(__fsub_rn(x2s[i0 + 1], __fmul_rn(2.0f, hi)), c2v[j]);
                    if (s0 < best[i0])     { best[i0]     = s0; bidx[i0]     = code; }
                    if (s1 < best[i0 + 1]) { best[i0 + 1] = s1; bidx[i0 + 1] = code; }
                }
            }
        }
    }

    // cross-thread (tx) reduction; overlay reduction arrays on the tile buffers
    __syncthreads();
    float* rS = &Xs[0][0][0];          // 128*16 floats = 2048 <= 4224 avail
    int*   rI = (int*)&Cs[0][0][0];
    #pragma unroll
    for (int i = 0; i < 8; i++) {
        int p = i >> 1, e = i & 1;
        int tl = (p < 2) ? (ty * 4 + p * 2 + e) : (64 + ty * 4 + (p - 2) * 2 + e);
        rS[tl * 16 + tx] = best[i];
        rI[tl * 16 + tx] = bidx[i];
    }
    __syncthreads();
    if (tid < TM) {
        float bs = rS[tid * 16];
        int   bi = rI[tid * 16];
        #pragma unroll
        for (int j = 1; j < 16; j++) {
            float s2 = rS[tid * 16 + j];
            int   i2 = rI[tid * 16 + j];
            if (s2 < bs || (s2 == bs && i2 < bi)) { bs = s2; bi = i2; }
        }
        g_partS[blockIdx.y][tb + tid] = bs;
        g_partI[blockIdx.y][tb + tid] = bi;
    }
}

// ---------------- K2b: merge K-split partials, counts, indices out ----------------
__global__ void k_merge(float* __restrict__ outF) {
    int t = blockIdx.x * blockDim.x + threadIdx.x;
    if (t >= Tt) return;
    float s0 = g_partS[0][t], s1 = g_partS[1][t];
    int   i0 = g_partI[0][t], i1 = g_partI[1][t];
    int bi = (s1 < s0) ? i1 : i0;   // tie -> i0 (lower index), matches jnp.argmin
    g_idx[t] = bi;
    outF[IDX_OFF + t] = (float)bi;
    atomicAdd(&g_counts[bi], 1.0f);
}

// ---------------- K3: dw scatter-add ----------------
__global__ void k_scatter(const float* __restrict__ x) {
    int n = Tt * (Dd / 4);
    for (int wi = blockIdx.x * blockDim.x + threadIdx.x; wi < n; wi += gridDim.x * blockDim.x) {
        int t = wi >> 7, dq = wi & 127;
        int idx = g_idx[t];
        float4 v = __ldg((const float4*)(x + (size_t)t * Dd) + dq);
        float* dst = g_dw + (size_t)idx * Dd + dq * 4;
        atomicAdd(dst + 0, v.x);
        atomicAdd(dst + 1, v.y);
        atomicAdd(dst + 2, v.z);
        atomicAdd(dst + 3, v.w);
    }
}

// ---------------- K4: EMA cluster + N reduce ----------------
__global__ void k_ema(const float* __restrict__ hc, const float* __restrict__ cnt) {
    int k = blockIdx.x * blockDim.x + threadIdx.x;
    if (k >= Kk) return;
    float count = __ldg(cnt);
    float bias = 1.f - powf(DECAYF, count + 1.f);
    float hcn = __ldg(hc + k) * DECAYF + (1.0f - DECAYF) * g_counts[k];
    float avg = hcn / bias;
    g_avgc[k] = avg;
    float s = avg;
    #pragma unroll
    for (int o = 16; o; o >>= 1) s += __shfl_xor_sync(0xffffffffu, s, o);
    if ((threadIdx.x & 31) == 0) atomicAdd(&g_N, s);
}

// ---------------- K5: codebook_new ----------------
__global__ void k_cbnew(const float* __restrict__ hdw, const float* __restrict__ cnt) {
    int n = Kk * (Dd / 4);
    int i = blockIdx.x * blockDim.x + threadIdx.x;
    if (i >= n) return;
    float count = __ldg(cnt);
    float bias = 1.f - powf(DECAYF, count + 1.f);
    float N = g_N;
    int k = i >> 7;
    float cc = (g_avgc[k] + EPSF) / (N + (float)Kk * EPSF) * N;
    float inv = 1.f / (bias * cc);
    float4 h = __ldg((const float4*)hdw + i);
    float4 w = *(((const float4*)g_dw) + i);
    float4 o;
    o.x = (h.x * DECAYF + (1.0f - DECAYF) * w.x) * inv;
    o.y = (h.y * DECAYF + (1.0f - DECAYF) * w.y) * inv;
    o.z = (h.z * DECAYF + (1.0f - DECAYF) * w.z) * inv;
    o.w = (h.w * DECAYF + (1.0f - DECAYF) * w.w) * inv;
    ((float4*)g_cbnew)[i] = o;
}

// ---------------- K6: gather quantized + loss ----------------
__global__ void k_quant(const float* __restrict__ x, float* __restrict__ out) {
    int n = Tt * (Dd / 4);
    float lsum = 0.f;
    for (int wi = blockIdx.x * blockDim.x + threadIdx.x; wi < n; wi += gridDim.x * blockDim.x) {
        int t = wi >> 7, dq = wi & 127;
        int idx = g_idx[t];
        float4 q  = *(((const float4*)(g_cbnew + (size_t)idx * Dd)) + dq);
        float4 xv = __ldg(((const float4*)x) + wi);
        float4 o;
        o.x = __fadd_rn(xv.x, __fsub_rn(q.x, xv.x));
        o.y = __fadd_rn(xv.y, __fsub_rn(q.y, xv.y));
        o.z = __fadd_rn(xv.z, __fsub_rn(q.z, xv.z));
        o.w = __fadd_rn(xv.w, __fsub_rn(q.w, xv.w));
        ((float4*)out)[wi] = o;
        float a = __fsub_rn(xv.x, o.x), b = __fsub_rn(xv.y, o.y);
        float c = __fsub_rn(xv.z, o.z), d = __fsub_rn(xv.w, o.w);
        lsum += a * a + b * b + c * c + d * d;
    }
    #pragma unroll
    for (int o = 16; o; o >>= 1) lsum += __shfl_xor_sync(0xffffffffu, lsum, o);
    __shared__ float red[8];
    int wid = threadIdx.x >> 5, lane = threadIdx.x & 31;
    if (lane == 0) red[wid] = lsum;
    __syncthreads();
    if (threadIdx.x == 0) {
        float s = 0.f;
        #pragma unroll
        for (int i = 0; i < 8; i++) s += red[i];
        atomicAdd(&g_loss, s);
    }
}

// ---------------- K7: finalize loss ----------------
__global__ void k_fin(float* __restrict__ out) {
    out[LOSS_OFF] = 0.5f * g_loss / (float)QN;
}

// ---------------- launch ----------------
extern "C" void kernel_launch(void* const* d_in, const int* in_sizes, int n_in,
                              void* d_out, int out_size) {
    const float* x   = (const float*)d_in[0];
    const float* cb  = (const float*)d_in[1];
    const float* hc  = (const float*)d_in[2];
    const float* hdw = (const float*)d_in[3];
    const float* cnt = (const float*)d_in[4];
    float* out = (float*)d_out;

    k_zero<<<2048, 256>>>();
    k_c2<<<(Kk * 32) / 256, 256>>>(cb);                 // warp per code row
    k_x2<<<(Tt * 32) / 256, 256>>>(x);                  // warp per token row
    {
        dim3 grid(Tt / TM, KSPLIT);                      // (128, 2)
        k_dist<<<grid, 256>>>(x, cb);
    }
    k_merge<<<Tt / 256, 256>>>(out);
    k_scatter<<<2048, 256>>>(x);
    k_ema<<<Kk / 256, 256>>>(hc, cnt);
    k_cbnew<<<(Kk * Dd / 4) / 256, 256>>>(hdw, cnt);
    k_quant<<<1024, 256>>>(x, out);
    k_fin<<<1, 1>>>(out);
}